// round 1
// baseline (speedup 1.0000x reference)
#include <cuda_runtime.h>

#define BB   2
#define T1   2048
#define T2V  2048
#define CC   512
#define HH   8
#define DD   64
#define NSRC 3

// Static scratch (allocation-free rule): Q, K(3), V(3), O accumuldel
__device__ float g_q[BB * T1 * CC];          // 8 MB
__device__ float g_k[NSRC * BB * T2V * CC];  // 24 MB
__device__ float g_v[NSRC * BB * T2V * CC];  // 24 MB
__device__ float g_o[BB * T1 * CC];          // 8 MB

// ---------------------------------------------------------------------------
// GEMM: out[m][n] = scale * (sum_k A[m][k]*W[k][n] + bias[n])
// A: [M,512] row-major, W: [512,512] row-major, M = 4096 always here.
// Tile 128x128x8, 256 threads, 8x8 per thread, double-buffered smem.
// ---------------------------------------------------------------------------
__global__ __launch_bounds__(256) void gemm512(
    const float* __restrict__ A, const float* __restrict__ W,
    const float* __restrict__ bias, float* __restrict__ out, float scale)
{
    __shared__ float As[2][8][128];   // [k][m]
    __shared__ float Bs[2][8][128];   // [k][n]

    const int tid = threadIdx.x;
    const int bm = blockIdx.y * 128;
    const int bn = blockIdx.x * 128;

    const int a_r = tid >> 1;            // 0..127
    const int a_k = (tid & 1) * 4;       // 0 or 4
    const int b_k = tid >> 5;            // 0..7
    const int b_n = (tid & 31) * 4;      // 0..124
    const int ty  = tid >> 4;            // 0..15
    const int tx  = tid & 15;            // 0..15

    float acc[8][8];
#pragma unroll
    for (int i = 0; i < 8; i++)
#pragma unroll
        for (int j = 0; j < 8; j++) acc[i][j] = 0.0f;

    // prologue: tile 0
    float4 av = *(const float4*)(A + (size_t)(bm + a_r) * CC + a_k);
    float4 bv = *(const float4*)(W + (size_t)b_k * CC + bn + b_n);
    As[0][a_k + 0][a_r] = av.x;
    As[0][a_k + 1][a_r] = av.y;
    As[0][a_k + 2][a_r] = av.z;
    As[0][a_k + 3][a_r] = av.w;
    *(float4*)&Bs[0][b_k][b_n] = bv;
    __syncthreads();

    int buf = 0;
    for (int kt = 0; kt < 64; kt++) {
        if (kt < 63) {
            av = *(const float4*)(A + (size_t)(bm + a_r) * CC + (kt + 1) * 8 + a_k);
            bv = *(const float4*)(W + (size_t)((kt + 1) * 8 + b_k) * CC + bn + b_n);
        }
#pragma unroll
        for (int k = 0; k < 8; k++) {
            float a[8], bb[8];
            *(float4*)&a[0]  = *(const float4*)&As[buf][k][ty * 8];
            *(float4*)&a[4]  = *(const float4*)&As[buf][k][ty * 8 + 4];
            *(float4*)&bb[0] = *(const float4*)&Bs[buf][k][tx * 8];
            *(float4*)&bb[4] = *(const float4*)&Bs[buf][k][tx * 8 + 4];
#pragma unroll
            for (int i = 0; i < 8; i++)
#pragma unroll
                for (int j = 0; j < 8; j++)
                    acc[i][j] += a[i] * bb[j];
        }
        if (kt < 63) {
            buf ^= 1;
            As[buf][a_k + 0][a_r] = av.x;
            As[buf][a_k + 1][a_r] = av.y;
            As[buf][a_k + 2][a_r] = av.z;
            As[buf][a_k + 3][a_r] = av.w;
            *(float4*)&Bs[buf][b_k][b_n] = bv;
            __syncthreads();
        }
    }

    float bcol[8];
    *(float4*)&bcol[0] = *(const float4*)(bias + bn + tx * 8);
    *(float4*)&bcol[4] = *(const float4*)(bias + bn + tx * 8 + 4);

#pragma unroll
    for (int i = 0; i < 8; i++) {
        float4 o0, o1;
        o0.x = scale * (acc[i][0] + bcol[0]);
        o0.y = scale * (acc[i][1] + bcol[1]);
        o0.z = scale * (acc[i][2] + bcol[2]);
        o0.w = scale * (acc[i][3] + bcol[3]);
        o1.x = scale * (acc[i][4] + bcol[4]);
        o1.y = scale * (acc[i][5] + bcol[5]);
        o1.z = scale * (acc[i][6] + bcol[6]);
        o1.w = scale * (acc[i][7] + bcol[7]);
        float* op = out + (size_t)(bm + ty * 8 + i) * CC + bn + tx * 8;
        *(float4*)op       = o0;
        *(float4*)(op + 4) = o1;
    }
}

// ---------------------------------------------------------------------------
// Flash attention, fp32. One block = one (b, h, 64-row Q tile). Loops the 3
// KV sources internally, each with its own online softmax; accumulates
// sum_i softmax(QK_i^T)V_i into registers, writes O once.
// 256 threads as 16x16; each thread owns a 4x4 micro-tile.
// smem: Qts[d][r], Kts[d][c], Vs[c][d], Pts[c][r]  (all 64x68 padded)
// ---------------------------------------------------------------------------
#define SPAD 68
#define ATTN_SMEM (4 * 64 * SPAD * 4)

__global__ __launch_bounds__(256) void attn64(
    const float* __restrict__ gq, const float* __restrict__ gk,
    const float* __restrict__ gv, float* __restrict__ go)
{
    extern __shared__ float sm[];
    float (*Qts)[SPAD] = (float(*)[SPAD])(sm);
    float (*Kts)[SPAD] = (float(*)[SPAD])(sm + 64 * SPAD);
    float (*Vs)[SPAD]  = (float(*)[SPAD])(sm + 2 * 64 * SPAD);
    float (*Pts)[SPAD] = (float(*)[SPAD])(sm + 3 * 64 * SPAD);

    const int tid = threadIdx.x;
    const int ty = tid >> 4;        // 0..15 -> Q rows ty*4..+4
    const int tx = tid & 15;        // 0..15 -> cols  tx*4..+4
    const int qt0 = blockIdx.x * 64;
    const int h = blockIdx.y;
    const int b = blockIdx.z;

    const int lr = tid >> 2;        // 0..63 tile row for loads
    const int lc = (tid & 3) * 4;   // 0,4,8,12

    // Q tile (already pre-scaled by 1/8 in the GEMM), stored transposed [d][r]
    {
        const float* qp = gq + ((size_t)(b * T1 + qt0 + lr)) * CC + h * DD;
#pragma unroll
        for (int q4 = 0; q4 < 4; q4++) {
            int d = lc + q4 * 16;
            float4 v = *(const float4*)(qp + d);
            Qts[d + 0][lr] = v.x;
            Qts[d + 1][lr] = v.y;
            Qts[d + 2][lr] = v.z;
            Qts[d + 3][lr] = v.w;
        }
    }

    float oacc[16];
#pragma unroll
    for (int i = 0; i < 16; i++) oacc[i] = 0.0f;

    for (int src = 0; src < NSRC; src++) {
        const float* K = gk + ((size_t)(src * BB + b)) * T2V * CC + h * DD;
        const float* V = gv + ((size_t)(src * BB + b)) * T2V * CC + h * DD;

        float o[16];
#pragma unroll
        for (int i = 0; i < 16; i++) o[i] = 0.0f;
        float mrow[4] = {-1e30f, -1e30f, -1e30f, -1e30f};
        float lrow[4] = {0.0f, 0.0f, 0.0f, 0.0f};

        for (int kt = 0; kt < T2V / 64; kt++) {
            __syncthreads();   // previous tile's Pts/Vs fully consumed; Q visible
            {
                const float* kp = K + (size_t)(kt * 64 + lr) * CC;
                const float* vp = V + (size_t)(kt * 64 + lr) * CC;
#pragma unroll
                for (int q4 = 0; q4 < 4; q4++) {
                    int d = lc + q4 * 16;
                    float4 kv = *(const float4*)(kp + d);
                    Kts[d + 0][lr] = kv.x;
                    Kts[d + 1][lr] = kv.y;
                    Kts[d + 2][lr] = kv.z;
                    Kts[d + 3][lr] = kv.w;
                    float4 vv = *(const float4*)(vp + d);
                    *(float4*)&Vs[lr][d] = vv;
                }
            }
            __syncthreads();

            // S = Q K^T (4x4 micro-tile per thread)
            float s[4][4];
#pragma unroll
            for (int j = 0; j < 4; j++)
#pragma unroll
                for (int jj = 0; jj < 4; jj++) s[j][jj] = 0.0f;

#pragma unroll
            for (int k = 0; k < 64; k++) {
                float4 a  = *(const float4*)&Qts[k][ty * 4];
                float4 bb = *(const float4*)&Kts[k][tx * 4];
                s[0][0] += a.x * bb.x; s[0][1] += a.x * bb.y; s[0][2] += a.x * bb.z; s[0][3] += a.x * bb.w;
                s[1][0] += a.y * bb.x; s[1][1] += a.y * bb.y; s[1][2] += a.y * bb.z; s[1][3] += a.y * bb.w;
                s[2][0] += a.z * bb.x; s[2][1] += a.z * bb.y; s[2][2] += a.z * bb.z; s[2][3] += a.z * bb.w;
                s[3][0] += a.w * bb.x; s[3][1] += a.w * bb.y; s[3][2] += a.w * bb.z; s[3][3] += a.w * bb.w;
            }

            // online softmax per row; row reduction across the 16 tx lanes
#pragma unroll
            for (int j = 0; j < 4; j++) {
                float mt = fmaxf(fmaxf(s[j][0], s[j][1]), fmaxf(s[j][2], s[j][3]));
#pragma unroll
                for (int w = 1; w < 16; w <<= 1)
                    mt = fmaxf(mt, __shfl_xor_sync(0xffffffffu, mt, w));
                float mnew = fmaxf(mrow[j], mt);
                float corr = __expf(mrow[j] - mnew);
                mrow[j] = mnew;
                lrow[j] *= corr;
                o[j * 4 + 0] *= corr;
                o[j * 4 + 1] *= corr;
                o[j * 4 + 2] *= corr;
                o[j * 4 + 3] *= corr;
                float ps = 0.0f;
#pragma unroll
                for (int jj = 0; jj < 4; jj++) {
                    float p = __expf(s[j][jj] - mnew);
                    ps += p;
                    Pts[tx * 4 + jj][ty * 4 + j] = p;   // transposed for PV
                }
#pragma unroll
                for (int w = 1; w < 16; w <<= 1)
                    ps += __shfl_xor_sync(0xffffffffu, ps, w);
                lrow[j] += ps;
            }
            __syncthreads();

            // O += P V
#pragma unroll
            for (int c = 0; c < 64; c++) {
                float4 p = *(const float4*)&Pts[c][ty * 4];
                float4 v = *(const float4*)&Vs[c][tx * 4];
                o[0]  += p.x * v.x; o[1]  += p.x * v.y; o[2]  += p.x * v.z; o[3]  += p.x * v.w;
                o[4]  += p.y * v.x; o[5]  += p.y * v.y; o[6]  += p.y * v.z; o[7]  += p.y * v.w;
                o[8]  += p.z * v.x; o[9]  += p.z * v.y; o[10] += p.z * v.z; o[11] += p.z * v.w;
                o[12] += p.w * v.x; o[13] += p.w * v.y; o[14] += p.w * v.z; o[15] += p.w * v.w;
            }
        }

#pragma unroll
        for (int j = 0; j < 4; j++) {
            float inv = 1.0f / lrow[j];
#pragma unroll
            for (int jj = 0; jj < 4; jj++)
                oacc[j * 4 + jj] += o[j * 4 + jj] * inv;
        }
    }

#pragma unroll
    for (int j = 0; j < 4; j++) {
        float4 w4 = make_float4(oacc[j * 4 + 0], oacc[j * 4 + 1],
                                oacc[j * 4 + 2], oacc[j * 4 + 3]);
        *(float4*)(go + ((size_t)(b * T1 + qt0 + ty * 4 + j)) * CC + h * DD + tx * 4) = w4;
    }
}

// ---------------------------------------------------------------------------
extern "C" void kernel_launch(void* const* d_in, const int* in_sizes, int n_in,
                              void* d_out, int out_size)
{
    const float* x  = (const float*)d_in[0];
    const float* y  = (const float*)d_in[1];
    const float* Wq = (const float*)d_in[2];
    const float* bq = (const float*)d_in[3];
    const float* Wk = (const float*)d_in[4];
    const float* bk = (const float*)d_in[5];
    const float* Wv = (const float*)d_in[6];
    const float* bv = (const float*)d_in[7];
    const float* Wp = (const float*)d_in[8];
    const float* bp = (const float*)d_in[9];
    float* out = (float*)d_out;

    float *pq, *pk, *pv, *po;
    cudaGetSymbolAddress((void**)&pq, g_q);
    cudaGetSymbolAddress((void**)&pk, g_k);
    cudaGetSymbolAddress((void**)&pv, g_v);
    cudaGetSymbolAddress((void**)&po, g_o);

    cudaFuncSetAttribute(attn64, cudaFuncAttributeMaxDynamicSharedMemorySize,
                         ATTN_SMEM);

    dim3 gg(CC / 128, (BB * T1) / 128);   // (4, 32)
    dim3 gb(256);

    // Q projection, pre-scaled by 1/sqrt(D) = 1/8
    gemm512<<<gg, gb>>>(x, Wq, bq, pq, 0.125f);

    // K/V projections for each of the 3 sources
    for (int i = 0; i < NSRC; i++) {
        const float* yi = y + (size_t)i * BB * T2V * CC;
        gemm512<<<gg, gb>>>(yi, Wk + (size_t)i * CC * CC, bk + i * CC,
                            pk + (size_t)i * BB * T2V * CC, 1.0f);
        gemm512<<<gg, gb>>>(yi, Wv + (size_t)i * CC * CC, bv + i * CC,
                            pv + (size_t)i * BB * T2V * CC, 1.0f);
    }

    // Attention (loops 3 sources internally)
    attn64<<<dim3(T1 / 64, HH, BB), 256, ATTN_SMEM>>>(pq, pk, pv, po);

    // Output projection -> d_out
    gemm512<<<gg, gb>>>(po, Wp, bp, out, 1.0f);
}